// round 5
// baseline (speedup 1.0000x reference)
#include <cuda_runtime.h>
#include <math.h>

// Shapes (fixed by the problem)
#define T 2048
#define B 32
#define H 1024
#define KSPLIT 16          // k-tiles of 64 for the v GEMM
#define NTG 128            // t-groups per b (T/16)

// Scratch (allocation-free rule: __device__ globals)
__device__ float g_vpart[KSPLIT][B][H];   // 2 MB split-k partials
__device__ float g_v[B][H];               // 128 KB  v = hid @ W
__device__ float g_scores[B][T];          // 256 KB  pre-softmax scores
__device__ float g_pm[B][NTG];            // per-tgroup local max
__device__ float g_ps[B][NTG];            // per-tgroup local sum of exp

// ---------------------------------------------------------------------------
// K1: v_part[ks][b][h] = sum over k in [ks*64, ks*64+64) of hid[b,k]*W[k,h]
// grid: (hchunk=2, bgroup=4, ksplit=16) = 128 blocks x 128 threads
// Each thread: 4 h (float4), 8 b, 64 k. Deterministic (no atomics).
// ---------------------------------------------------------------------------
__global__ void __launch_bounds__(128) k_vpart(const float* __restrict__ hid,
                                               const float* __restrict__ W) {
    __shared__ float hid_s[8][64];
    const int tid   = threadIdx.x;          // 0..127
    const int h0    = blockIdx.x * 512 + tid * 4;
    const int bbase = blockIdx.y * 8;
    const int kbase = blockIdx.z * 64;

    for (int i = tid; i < 8 * 64; i += 128) {
        int bb = i >> 6, kk = i & 63;
        hid_s[bb][kk] = hid[(bbase + bb) * H + kbase + kk];
    }
    __syncthreads();

    float4 acc[8];
#pragma unroll
    for (int bb = 0; bb < 8; bb++) acc[bb] = make_float4(0.f, 0.f, 0.f, 0.f);

#pragma unroll 4
    for (int kk = 0; kk < 64; kk++) {
        float4 w = *reinterpret_cast<const float4*>(&W[(size_t)(kbase + kk) * H + h0]);
#pragma unroll
        for (int bb = 0; bb < 8; bb++) {
            float hv = hid_s[bb][kk];
            acc[bb].x += hv * w.x;
            acc[bb].y += hv * w.y;
            acc[bb].z += hv * w.z;
            acc[bb].w += hv * w.w;
        }
    }

#pragma unroll
    for (int bb = 0; bb < 8; bb++) {
        *reinterpret_cast<float4*>(&g_vpart[blockIdx.z][bbase + bb][h0]) = acc[bb];
    }
}

// ---------------------------------------------------------------------------
// K2: v[b][h] = sum over ksplit of v_part   (32768 elems; vpart sits in L2)
// ---------------------------------------------------------------------------
__global__ void __launch_bounds__(256) k_vreduce() {
    int idx = blockIdx.x * blockDim.x + threadIdx.x;
    const float* vp = &g_vpart[0][0][0];
    float* v = &g_v[0][0];
    if (idx < B * H) {
        float s = 0.f;
#pragma unroll
        for (int p = 0; p < KSPLIT; p++) s += vp[p * (B * H) + idx];
        v[idx] = s;
    }
}

// ---------------------------------------------------------------------------
// K3: scores[b][t] = enc[t,b,:] . v[b,:]   (R2 structure, untouched stream)
// One warp owns one b and 16 consecutive t's; v[b] in registers. All 128
// loads per warp are independent (max MLP); one pipelined butterfly at the
// end; THEN (loads all retired) compute the per-tgroup softmax partial
// (max, sum-exp) redundantly in all lanes -- zero cost to the stream.
// grid: 512 blocks x 256 threads = 4096 warps = 32 b x 128 t-groups
// ---------------------------------------------------------------------------
__global__ void __launch_bounds__(256) k_scores(const float* __restrict__ enc) {
    const int warp = threadIdx.x >> 5;
    const int lane = threadIdx.x & 31;
    const int gw   = blockIdx.x * 8 + warp;     // 0..4095
    const int b    = gw & 31;
    const int tg   = gw >> 5;                   // 0..127
    const int tbase = tg * 16;

    // v[b] into registers: 8 float4 per lane (lane covers h = i*128 + lane*4)
    float4 vreg[8];
#pragma unroll
    for (int i = 0; i < 8; i++) {
        vreg[i] = *reinterpret_cast<const float4*>(&g_v[b][i * 128 + lane * 4]);
    }

    float acc[16];
#pragma unroll
    for (int tt = 0; tt < 16; tt++) {
        const int t = tbase + tt;
        const float4* e = reinterpret_cast<const float4*>(
            enc + ((size_t)t * B + b) * H) + lane;   // lane*4 floats in
        float4 a = make_float4(0.f, 0.f, 0.f, 0.f);
#pragma unroll
        for (int i = 0; i < 8; i++) {
            float4 ev = __ldcs(&e[i * 32]);          // h = i*128 + lane*4
            a.x += ev.x * vreg[i].x;
            a.y += ev.y * vreg[i].y;
            a.z += ev.z * vreg[i].z;
            a.w += ev.w * vreg[i].w;
        }
        acc[tt] = (a.x + a.y) + (a.z + a.w);
    }

    // Pipelined multi-value butterfly: 16 independent 5-stage chains.
    // After this, ALL lanes hold all 16 final sums.
#pragma unroll
    for (int off = 16; off > 0; off >>= 1) {
#pragma unroll
        for (int i = 0; i < 16; i++)
            acc[i] += __shfl_xor_sync(0xFFFFFFFFu, acc[i], off);
    }

    // local softmax partial over the 16 t's (every lane redundantly)
    float mg = acc[0];
#pragma unroll
    for (int i = 1; i < 16; i++) mg = fmaxf(mg, acc[i]);
    float sg = 0.f;
#pragma unroll
    for (int i = 0; i < 16; i++) sg += __expf(acc[i] - mg);

    if (lane == 0) {
#pragma unroll
        for (int i = 0; i < 16; i++) g_scores[b][tbase + i] = acc[i];
        g_pm[b][tg] = mg;
        g_ps[b][tg] = sg;
    }
}

// ---------------------------------------------------------------------------
// K4: out[b,0,t] = exp(scores[b][t] - M[b]) / S[b]
// 64 blocks x 256 threads; block covers (b = blk>>1, half = blk&1, 1024 t).
// Each warp redundantly merges the 128 (m,s) partials of its b (8 loads +
// 2 butterflies, no smem/sync), then writes its 128 outputs as float4.
// ---------------------------------------------------------------------------
__global__ void __launch_bounds__(256) k_finish(float* __restrict__ out) {
    const int b    = blockIdx.x >> 1;
    const int half = blockIdx.x & 1;
    const int warp = threadIdx.x >> 5;
    const int lane = threadIdx.x & 31;

    // merge 128 partials -> (M, 1/S); xor-butterflies leave result in all lanes
    float m[4], s[4];
#pragma unroll
    for (int j = 0; j < 4; j++) {
        m[j] = g_pm[b][lane + 32 * j];
        s[j] = g_ps[b][lane + 32 * j];
    }
    float M = fmaxf(fmaxf(m[0], m[1]), fmaxf(m[2], m[3]));
#pragma unroll
    for (int off = 16; off > 0; off >>= 1)
        M = fmaxf(M, __shfl_xor_sync(0xFFFFFFFFu, M, off));
    float S = 0.f;
#pragma unroll
    for (int j = 0; j < 4; j++) S += s[j] * __expf(m[j] - M);
#pragma unroll
    for (int off = 16; off > 0; off >>= 1)
        S += __shfl_xor_sync(0xFFFFFFFFu, S, off);
    const float inv = 1.f / S;

    // 128 t's per warp: lane handles 4 consecutive t as one float4
    const int t0 = half * 1024 + warp * 128 + lane * 4;
    float4 sc = *reinterpret_cast<const float4*>(&g_scores[b][t0]);
    float4 o;
    o.x = __expf(sc.x - M) * inv;
    o.y = __expf(sc.y - M) * inv;
    o.z = __expf(sc.z - M) * inv;
    o.w = __expf(sc.w - M) * inv;
    *reinterpret_cast<float4*>(&out[(size_t)b * T + t0]) = o;
}

// ---------------------------------------------------------------------------
// Inputs (metadata order): hidden [1,B,H], encoderOutput [T,B,H], W [H,H], b [H]
// Output: [B,1,T] float32.  Bias is constant in t -> cancels in softmax.
// ---------------------------------------------------------------------------
extern "C" void kernel_launch(void* const* d_in, const int* in_sizes, int n_in,
                              void* d_out, int out_size) {
    const float* hid = (const float*)d_in[0];
    const float* enc = (const float*)d_in[1];
    const float* W   = (const float*)d_in[2];
    (void)in_sizes; (void)n_in; (void)out_size;
    float* out = (float*)d_out;

    k_vpart<<<dim3(2, 4, KSPLIT), 128>>>(hid, W);
    k_vreduce<<<(B * H + 255) / 256, 256>>>();
    k_scores<<<512, 256>>>(enc);
    k_finish<<<64, 256>>>(out);
}